// round 9
// baseline (speedup 1.0000x reference)
#include <cuda_runtime.h>
#include <cuda_bf16.h>
#include <cfloat>
#include <math.h>
#include <stdint.h>

// Shapes fixed by the dataset
#define BATCH 4        // 32 / snip
#define SNIP  8
#define CCH   256
#define HWP   784      // 28*28
#define THWC  6272     // SNIP*HWP
#define NTOT  25088    // BATCH*THWC = 32*784
#define TK    5

// ---------------- device scratch (no runtime allocation allowed) ----------------
__device__ float g_Xk [BATCH*CCH*THWC];   // [b][c][j]  k-major   (GEMM operand)
__device__ float g_Xt [BATCH*THWC*CCH];   // [b][j][c]  row-major (gather / norms)
__device__ float g_Y  [NTOT*CCH];         // gathered-max [n][c], n = bs*784+hw
__device__ float g_inv[NTOT];             // 1/||x_j|| per (b,j)
__device__ float g_pv [BATCH*3*THWC*TK];  // partial top-5 values (per i-slice)
__device__ int   g_pi [BATCH*3*THWC*TK];  // partial top-5 indices
__device__ int   g_top[NTOT*TK];          // merged top-5 indices
__device__ float g_part[98*512];          // BN partials (sum, sumsq)
__device__ float g_ab [2*CCH];            // BN scale / shift
__device__ float g_Wt [CCH*CCH];          // conv_w transposed [c][o]

// ---------------- cp.async helpers ----------------
__device__ __forceinline__ void cp16(void* smem, const void* g){
  uint32_t s = (uint32_t)__cvta_generic_to_shared(smem);
  asm volatile("cp.async.cg.shared.global [%0], [%1], 16;\n" :: "r"(s), "l"(g));
}
__device__ __forceinline__ void cp_commit(){ asm volatile("cp.async.commit_group;\n" ::: "memory"); }
template<int N> __device__ __forceinline__ void cp_wait(){ asm volatile("cp.async.wait_group %0;\n" :: "n"(N) : "memory"); }

// running top-5 insert (strict >, ascending-i scan keeps smallest index on ties)
#define INS5(v, i)                                                                   \
  if ((v) > tv4){                                                                    \
    if ((v) > tv2){                                                                  \
      if ((v) > tv1){                                                                \
        if ((v) > tv0){ tv4=tv3;ti4=ti3; tv3=tv2;ti3=ti2; tv2=tv1;ti2=ti1;           \
                        tv1=tv0;ti1=ti0; tv0=(v);ti0=(i); }                          \
        else { tv4=tv3;ti4=ti3; tv3=tv2;ti3=ti2; tv2=tv1;ti2=ti1; tv1=(v);ti1=(i); } \
      } else { tv4=tv3;ti4=ti3; tv3=tv2;ti3=ti2; tv2=(v);ti2=(i); }                  \
    } else {                                                                         \
      if ((v) > tv3){ tv4=tv3;ti4=ti3; tv3=(v);ti3=(i); }                            \
      else { tv4=(v); ti4=(i); }                                                     \
    }                                                                                \
  }

// merge insert with total order (val desc, idx asc) — exact cross-thread/slice ties
#define BET(v,i,V,I) ((v) > (V) || ((v)==(V) && (i) < (I)))
#define MINS5(v, i)                                                                  \
  if (BET(v,i,tv4,ti4)){                                                             \
    if (BET(v,i,tv2,ti2)){                                                           \
      if (BET(v,i,tv1,ti1)){                                                         \
        if (BET(v,i,tv0,ti0)){ tv4=tv3;ti4=ti3; tv3=tv2;ti3=ti2; tv2=tv1;ti2=ti1;    \
                               tv1=tv0;ti1=ti0; tv0=(v);ti0=(i); }                   \
        else { tv4=tv3;ti4=ti3; tv3=tv2;ti3=ti2; tv2=tv1;ti2=ti1; tv1=(v);ti1=(i); } \
      } else { tv4=tv3;ti4=ti3; tv3=tv2;ti3=ti2; tv2=(v);ti2=(i); }                  \
    } else {                                                                         \
      if (BET(v,i,tv3,ti3)){ tv4=tv3;ti4=ti3; tv3=(v);ti3=(i); }                     \
      else { tv4=(v); ti4=(i); }                                                     \
    }                                                                                \
  }

// ---------------- A1: repack x -> Xk [b][c][j] (coalesced permutation copy) ------
__global__ void k_repack(const float* __restrict__ x){
  int idx = blockIdx.x*256 + threadIdx.x;          // float4 id; total 1,605,632
  int hw4 = idx % 196;
  int r   = idx / 196;
  int c   = r & 255;
  int bs  = r >> 8;
  int b = bs >> 3, t = bs & 7;
  float4 v = ((const float4*)x)[idx];
  ((float4*)g_Xk)[(b*CCH + c)*1568 + t*196 + hw4] = v;
}

// ---------------- A2: tiled transpose x -> Xt [b][j][c] ----------------
__global__ void k_xt(const float* __restrict__ x){
  __shared__ float tile[32][33];
  int bs = blockIdx.z, cb = blockIdx.y*32, hb = blockIdx.x*32;
  int tx = threadIdx.x, ty = threadIdx.y;
  #pragma unroll
  for (int q=0;q<4;q++){
    int c = cb + ty + q*8, hw = hb + tx;
    if (hw < HWP) tile[ty+q*8][tx] = x[((size_t)bs*CCH + c)*HWP + hw];
  }
  __syncthreads();
  int b = bs >> 3, t = bs & 7;
  #pragma unroll
  for (int q=0;q<4;q++){
    int hw = hb + ty + q*8, c = cb + tx;
    if (hw < HWP) g_Xt[((size_t)b*THWC + t*HWP + hw)*CCH + c] = tile[tx][ty+q*8];
  }
}

// ---------------- A3: per-column inverse norms ----------------
__global__ void k_norm(){
  int w = threadIdx.x >> 5, lane = threadIdx.x & 31;
  int row = blockIdx.x*8 + w;                      // 0..25087
  const float* rp = g_Xt + (size_t)row*CCH;
  float s = 0.f;
  #pragma unroll
  for (int q=0;q<8;q++){ float f = rp[lane + q*32]; s = fmaf(f, f, s); }
  #pragma unroll
  for (int o=16;o;o>>=1) s += __shfl_xor_sync(0xffffffffu, s, o);
  if (lane == 0) g_inv[row] = rsqrtf(s);
}

// ---------------- A4: transpose conv_w -> Wt [c][o] ----------------
__global__ void k_wt(const float* __restrict__ w){
  int c = blockIdx.x, o = threadIdx.x;
  g_Wt[c*CCH + o] = w[o*CCH + c];
}

// ---------------- B: Gram GEMM + fused streaming top-5 ----------------
// grid (49 j-tiles, 3 i-slices, 4 batches); 256 threads; 1 block/SM
__global__ void __launch_bounds__(256,1) k_corr(){
  extern __shared__ float sm[];
  float* Bs = sm;                    // [256][128] full-K j panel   (128 KB)
  float* As = sm + 32768;            // [2][16][128] A chunk ping-pong (16 KB)
  float* Sv = sm + 32768 + 4096;     // [128][129] scaled tile      (64.5 KB)
  __shared__ float s_invj[128];
  __shared__ float s_invi[128];

  const int tid = threadIdx.x;
  const int tx = tid & 15, ty = tid >> 4;
  const int jt = blockIdx.x, sl = blockIdx.y, b = blockIdx.z;
  const int jbase = jt*128;
  const int t0 = (sl==0) ? 0 : (17 + (sl-1)*16);
  const int nt = (sl==0) ? 17 : 16;
  const float* Xkb = g_Xk + (size_t)b*CCH*THWC;

  // load j panel: Bs[k][jj]
  #pragma unroll
  for (int q=0;q<32;q++){
    int id = tid + q*256;
    int k = id >> 5, jv = id & 31;
    ((float4*)Bs)[k*32 + jv] = *(const float4*)(Xkb + (size_t)k*THWC + jbase + jv*4);
  }
  if (tid < 128) s_invj[tid] = g_inv[b*THWC + jbase + tid];
  __syncthreads();

  const int col = tid & 127, half = tid >> 7;
  float tv0=-3e38f, tv1=-3e38f, tv2=-3e38f, tv3=-3e38f, tv4=-3e38f;
  int   ti0=0, ti1=0, ti2=0, ti3=0, ti4=0;

  for (int it = t0; it < t0 + nt; ++it){
    const int ibase = it*128;
    if (tid < 128) s_invi[tid] = g_inv[b*THWC + ibase + tid];

    // prologue: chunk 0 -> buffer 0
    {
      const float* src = Xkb + ibase;
      #pragma unroll
      for (int q=0;q<2;q++){
        int id = tid + q*256; int kk = id>>5, iv = id&31;
        cp16(As + kk*128 + iv*4, src + (size_t)kk*THWC + iv*4);
      }
      cp_commit();
    }

    float acc[8][8];
    #pragma unroll
    for (int r=0;r<8;r++)
      #pragma unroll
      for (int c=0;c<8;c++) acc[r][c] = 0.f;

    for (int kc=0; kc<16; ++kc){
      const int cur = kc & 1;
      if (kc < 15){
        const float* src = Xkb + (size_t)(kc+1)*16*THWC + ibase;
        float* dst = As + (cur^1)*2048;
        #pragma unroll
        for (int q=0;q<2;q++){
          int id = tid + q*256; int kk = id>>5, iv = id&31;
          cp16(dst + kk*128 + iv*4, src + (size_t)kk*THWC + iv*4);
        }
        cp_commit();
        cp_wait<1>();
      } else {
        cp_wait<0>();
      }
      __syncthreads();

      const float* Ab = As + cur*2048;
      #pragma unroll
      for (int kk=0;kk<16;kk++){
        float4 a0 = *(const float4*)(Ab + kk*128 + ty*8);
        float4 a1 = *(const float4*)(Ab + kk*128 + ty*8 + 4);
        const float* Bp = Bs + (kc*16+kk)*128 + tx*8;
        float4 b0 = *(const float4*)(Bp);
        float4 b1 = *(const float4*)(Bp + 4);
        float av[8] = {a0.x,a0.y,a0.z,a0.w,a1.x,a1.y,a1.z,a1.w};
        float bv[8] = {b0.x,b0.y,b0.z,b0.w,b1.x,b1.y,b1.z,b1.w};
        #pragma unroll
        for (int r=0;r<8;r++)
          #pragma unroll
          for (int c=0;c<8;c++)
            acc[r][c] = fmaf(av[r], bv[c], acc[r][c]);
      }
      __syncthreads();
    }

    // epilogue: scale by inverse norms, mask same-frame blocks, stage to Sv
    // (8-row / 8-col micro-tiles never cross a 784-frame boundary: 8 | 784)
    const bool masked = ((ibase + ty*8)/HWP) == ((jbase + tx*8)/HWP);
    #pragma unroll
    for (int r=0;r<8;r++){
      float ivn = s_invi[ty*8 + r];
      #pragma unroll
      for (int c=0;c<8;c++){
        float v = masked ? -1.0f : acc[r][c]*ivn*s_invj[tx*8+c];
        Sv[(ty*8+r)*129 + tx*8 + c] = v;
      }
    }
    __syncthreads();

    // streaming scan: 2 threads per column, 64 ascending rows each
    const int rbase = half*64;
    #pragma unroll 4
    for (int r=0;r<64;r++){
      float v = Sv[(rbase+r)*129 + col];
      int gi = ibase + rbase + r;
      INS5(v, gi);
    }
    __syncthreads();
  }

  // merge halves (reuse Sv as staging), write slice partials
  float* shv = Sv;
  int*   shi = (int*)(Sv + 128*TK);
  if (half == 1){
    shv[col*5+0]=tv0; shv[col*5+1]=tv1; shv[col*5+2]=tv2; shv[col*5+3]=tv3; shv[col*5+4]=tv4;
    shi[col*5+0]=ti0; shi[col*5+1]=ti1; shi[col*5+2]=ti2; shi[col*5+3]=ti3; shi[col*5+4]=ti4;
  }
  __syncthreads();
  if (half == 0){
    #pragma unroll
    for (int q=0;q<5;q++){ float v = shv[col*5+q]; int i = shi[col*5+q]; MINS5(v, i); }
    size_t base = ((size_t)(b*3 + sl)*THWC + jbase + col)*TK;
    g_pv[base+0]=tv0; g_pv[base+1]=tv1; g_pv[base+2]=tv2; g_pv[base+3]=tv3; g_pv[base+4]=tv4;
    g_pi[base+0]=ti0; g_pi[base+1]=ti1; g_pi[base+2]=ti2; g_pi[base+3]=ti3; g_pi[base+4]=ti4;
  }
}

// ---------------- C: merge 3 slice-partials -> final top-5 indices ----------------
__global__ void k_merge(){
  int gj = blockIdx.x*256 + threadIdx.x;   // 0..25087
  int b = gj / THWC, j = gj - b*THWC;
  float tv0=-3e38f, tv1=-3e38f, tv2=-3e38f, tv3=-3e38f, tv4=-3e38f;
  int   ti0=0, ti1=0, ti2=0, ti3=0, ti4=0;
  #pragma unroll
  for (int sl=0;sl<3;sl++){
    size_t base = ((size_t)(b*3 + sl)*THWC + j)*TK;
    #pragma unroll
    for (int q=0;q<5;q++){
      float v = g_pv[base+q]; int i = g_pi[base+q];
      MINS5(v, i);
    }
  }
  g_top[(size_t)gj*5+0]=ti0; g_top[(size_t)gj*5+1]=ti1; g_top[(size_t)gj*5+2]=ti2;
  g_top[(size_t)gj*5+3]=ti3; g_top[(size_t)gj*5+4]=ti4;
}

// ---------------- D: gather 5 columns, elementwise channel max ----------------
__global__ void k_gather(){
  int warp = threadIdx.x >> 5, lane = threadIdx.x & 31;
  int n = blockIdx.x*8 + warp;             // 0..25087
  int b = n / THWC;
  const int* tp = g_top + (size_t)n*5;
  int i0 = tp[0], i1 = tp[1], i2 = tp[2], i3 = tp[3], i4 = tp[4];
  const float4* X = (const float4*)(g_Xt + (size_t)b*THWC*CCH);
  float4* Yo = (float4*)(g_Y + (size_t)n*CCH);
  #pragma unroll
  for (int q=0;q<2;q++){
    int p = lane + q*32;                   // 0..63 float4 within a 256-float row
    float4 m  = X[(size_t)i0*64 + p];
    float4 v1 = X[(size_t)i1*64 + p];
    float4 v2 = X[(size_t)i2*64 + p];
    float4 v3 = X[(size_t)i3*64 + p];
    float4 v4 = X[(size_t)i4*64 + p];
    m.x = fmaxf(fmaxf(fmaxf(m.x,v1.x), fmaxf(v2.x,v3.x)), v4.x);
    m.y = fmaxf(fmaxf(fmaxf(m.y,v1.y), fmaxf(v2.y,v3.y)), v4.y);
    m.z = fmaxf(fmaxf(fmaxf(m.z,v1.z), fmaxf(v2.z,v3.z)), v4.z);
    m.w = fmaxf(fmaxf(fmaxf(m.w,v1.w), fmaxf(v2.w,v3.w)), v4.w);
    Yo[p] = m;
  }
}

// ---------------- E: BN statistics ----------------
__global__ void k_bnstat(){
  int t = threadIdx.x;
  const float* Yp = g_Y + (size_t)blockIdx.x*256*CCH;
  float s = 0.f, sq = 0.f;
  for (int r=0;r<256;r++){
    float v = Yp[(size_t)r*CCH + t];
    s += v; sq = fmaf(v, v, sq);
  }
  g_part[blockIdx.x*512 + t]       = s;
  g_part[blockIdx.x*512 + 256 + t] = sq;
}

__global__ void k_bnfin(const float* __restrict__ gamma, const float* __restrict__ beta){
  int t = threadIdx.x;
  float s = 0.f, sq = 0.f;
  for (int blk=0;blk<98;blk++){
    s  += g_part[blk*512 + t];
    sq += g_part[blk*512 + 256 + t];
  }
  const float invN = 1.0f/25088.0f;
  float mean = s*invN;
  float var  = sq*invN - mean*mean;
  float a = gamma[t]*rsqrtf(var + 1e-5f);
  g_ab[t]       = a;
  g_ab[256 + t] = beta[t] - mean*a;
}

// ---------------- F: fused BN+relu + 1x1 conv GEMM + bias + residual -------------
// grid (196 n-tiles, 2 o-tiles); 256 threads
__global__ void __launch_bounds__(256,1) k_conv(const float* __restrict__ cbv,
                                                const float* __restrict__ x,
                                                float* __restrict__ out){
  extern __shared__ float sm[];
  float* Ws = sm;            // [256][128] weight panel [k][o]  (128 KB)
  float* As = sm + 32768;    // [128][16]  z chunk (8 KB, single buffer)
  __shared__ float s_a[256], s_b[256], s_cb[128];

  const int tid = threadIdx.x;
  const int tx = tid & 15, ty = tid >> 4;
  const int nbase = blockIdx.x*128, obase = blockIdx.y*128;

  #pragma unroll
  for (int q=0;q<32;q++){
    int id = tid + q*256; int k = id>>5, ov = id&31;
    ((float4*)Ws)[k*32 + ov] = *(const float4*)(g_Wt + k*CCH + obase + ov*4);
  }
  s_a[tid] = g_ab[tid];
  s_b[tid] = g_ab[256 + tid];
  if (tid < 128) s_cb[tid] = cbv[obase + tid];

  float acc[8][8];
  #pragma unroll
  for (int r=0;r<8;r++)
    #pragma unroll
    for (int c=0;c<8;c++) acc[r][c] = 0.f;

  const int nn = tid >> 1, hf = tid & 1;
  const float* Yrow = g_Y + (size_t)(nbase + nn)*CCH + hf*8;

  for (int kc=0;kc<16;kc++){
    __syncthreads();           // protect As from previous iteration's readers
    float4 v0 = *(const float4*)(Yrow + kc*16);
    float4 v1 = *(const float4*)(Yrow + kc*16 + 4);
    int kg = kc*16 + hf*8;
    float vv[8] = {v0.x,v0.y,v0.z,v0.w,v1.x,v1.y,v1.z,v1.w};
    float z[8];
    #pragma unroll
    for (int q=0;q<8;q++) z[q] = fmaxf(fmaf(vv[q], s_a[kg+q], s_b[kg+q]), 0.f);
    *(float4*)(As + nn*16 + hf*8)     = make_float4(z[0],z[1],z[2],z[3]);
    *(float4*)(As + nn*16 + hf*8 + 4) = make_float4(z[4],z[5],z[6],z[7]);
    __syncthreads();

    #pragma unroll
    for (int kk=0;kk<16;kk++){
      float av[8];
      #pragma unroll
      for (int r=0;r<8;r++) av[r] = As[(ty*8+r)*16 + kk];
      const float* Bp = Ws + (kc*16+kk)*128 + tx*8;
      float4 b0 = *(const float4*)(Bp);
      float4 b1 = *(const float4*)(Bp + 4);
      float bv[8] = {b0.x,b0.y,b0.z,b0.w,b1.x,b1.y,b1.z,b1.w};
      #pragma unroll
      for (int r=0;r<8;r++)
        #pragma unroll
        for (int c=0;c<8;c++)
          acc[r][c] = fmaf(av[r], bv[c], acc[r][c]);
    }
  }

  // epilogue: bias + residual, write NCHW (thread's 8 n stay in one frame: 8|784)
  const int n0 = nbase + ty*8;
  const int bs = n0 / HWP;
  const int hw0 = n0 - bs*HWP;
  const float* xb = x   + (size_t)bs*CCH*HWP;
  float*       ob = out + (size_t)bs*CCH*HWP;
  #pragma unroll
  for (int c=0;c<8;c++){
    int o = obase + tx*8 + c;
    float bias = s_cb[tx*8 + c];
    size_t off = (size_t)o*HWP + hw0;
    float4 i0 = *(const float4*)(xb + off);
    float4 i1 = *(const float4*)(xb + off + 4);
    float4 r0 = make_float4(acc[0][c]+bias+i0.x, acc[1][c]+bias+i0.y,
                            acc[2][c]+bias+i0.z, acc[3][c]+bias+i0.w);
    float4 r1 = make_float4(acc[4][c]+bias+i1.x, acc[5][c]+bias+i1.y,
                            acc[6][c]+bias+i1.z, acc[7][c]+bias+i1.w);
    *(float4*)(ob + off)     = r0;
    *(float4*)(ob + off + 4) = r1;
  }
}

// ---------------- launch ----------------
extern "C" void kernel_launch(void* const* d_in, const int* in_sizes, int n_in,
                              void* d_out, int out_size){
  (void)in_sizes; (void)n_in; (void)out_size;
  const float* x      = (const float*)d_in[0];
  const float* gamma  = (const float*)d_in[1];
  const float* beta   = (const float*)d_in[2];
  const float* conv_w = (const float*)d_in[3];
  const float* conv_b = (const float*)d_in[4];
  float* out = (float*)d_out;

  cudaFuncSetAttribute(k_corr, cudaFuncAttributeMaxDynamicSharedMemorySize, 213504);
  cudaFuncSetAttribute(k_conv, cudaFuncAttributeMaxDynamicSharedMemorySize, 139264);

  k_repack<<<6272, 256>>>(x);
  k_xt<<<dim3(25, 8, 32), dim3(32, 8)>>>(x);
  k_norm<<<3136, 256>>>();
  k_wt<<<256, 256>>>(conv_w);
  k_corr<<<dim3(49, 3, 4), 256, 213504>>>();
  k_merge<<<98, 256>>>();
  k_gather<<<3136, 256>>>();
  k_bnstat<<<98, 256>>>();
  k_bnfin<<<1, 256>>>(gamma, beta);
  k_conv<<<dim3(196, 2), 256, 139264>>>(conv_b, x, out);
}

// round 10
// speedup vs baseline: 1.0003x; 1.0003x over previous
#include <cuda_runtime.h>
#include <cuda_bf16.h>
#include <cfloat>
#include <math.h>
#include <stdint.h>

// Shapes fixed by the dataset
#define BATCH 4        // 32 / snip
#define SNIP  8
#define CCH   256
#define HWP   784      // 28*28
#define THWC  6272     // SNIP*HWP
#define NTOT  25088    // BATCH*THWC = 32*784
#define TK    5

// ---------------- device scratch (no runtime allocation allowed) ----------------
__device__ float g_Xk [BATCH*CCH*THWC];   // [b][c][j]  k-major   (GEMM operand)
__device__ float g_Xt [BATCH*THWC*CCH];   // [b][j][c]  row-major (gather / norms)
__device__ float g_Y  [NTOT*CCH];         // gathered-max [n][c], n = bs*784+hw
__device__ float g_inv[NTOT];             // 1/||x_j|| per (b,j)
__device__ float g_pv [BATCH*3*THWC*TK];  // partial top-5 values (per i-slice)
__device__ int   g_pi [BATCH*3*THWC*TK];  // partial top-5 indices
__device__ int   g_top[NTOT*TK];          // merged top-5 indices
__device__ float g_part[98*512];          // BN partials (sum, sumsq)
__device__ float g_ab [2*CCH];            // BN scale / shift
__device__ float g_Wt [CCH*CCH];          // conv_w transposed [c][o]

// ---------------- cp.async helpers ----------------
__device__ __forceinline__ void cp16(void* smem, const void* g){
  uint32_t s = (uint32_t)__cvta_generic_to_shared(smem);
  asm volatile("cp.async.cg.shared.global [%0], [%1], 16;\n" :: "r"(s), "l"(g));
}
__device__ __forceinline__ void cp_commit(){ asm volatile("cp.async.commit_group;\n" ::: "memory"); }
template<int N> __device__ __forceinline__ void cp_wait(){ asm volatile("cp.async.wait_group %0;\n" :: "n"(N) : "memory"); }

// running top-5 insert (strict >, ascending-i scan keeps smallest index on ties)
#define INS5(v, i)                                                                   \
  if ((v) > tv4){                                                                    \
    if ((v) > tv2){                                                                  \
      if ((v) > tv1){                                                                \
        if ((v) > tv0){ tv4=tv3;ti4=ti3; tv3=tv2;ti3=ti2; tv2=tv1;ti2=ti1;           \
                        tv1=tv0;ti1=ti0; tv0=(v);ti0=(i); }                          \
        else { tv4=tv3;ti4=ti3; tv3=tv2;ti3=ti2; tv2=tv1;ti2=ti1; tv1=(v);ti1=(i); } \
      } else { tv4=tv3;ti4=ti3; tv3=tv2;ti3=ti2; tv2=(v);ti2=(i); }                  \
    } else {                                                                         \
      if ((v) > tv3){ tv4=tv3;ti4=ti3; tv3=(v);ti3=(i); }                            \
      else { tv4=(v); ti4=(i); }                                                     \
    }                                                                                \
  }

// merge insert with total order (val desc, idx asc) — exact cross-thread/slice ties
#define BET(v,i,V,I) ((v) > (V) || ((v)==(V) && (i) < (I)))
#define MINS5(v, i)                                                                  \
  if (BET(v,i,tv4,ti4)){                                                             \
    if (BET(v,i,tv2,ti2)){                                                           \
      if (BET(v,i,tv1,ti1)){                                                         \
        if (BET(v,i,tv0,ti0)){ tv4=tv3;ti4=ti3; tv3=tv2;ti3=ti2; tv2=tv1;ti2=ti1;    \
                               tv1=tv0;ti1=ti0; tv0=(v);ti0=(i); }                   \
        else { tv4=tv3;ti4=ti3; tv3=tv2;ti3=ti2; tv2=tv1;ti2=ti1; tv1=(v);ti1=(i); } \
      } else { tv4=tv3;ti4=ti3; tv3=tv2;ti3=ti2; tv2=(v);ti2=(i); }                  \
    } else {                                                                         \
      if (BET(v,i,tv3,ti3)){ tv4=tv3;ti4=ti3; tv3=(v);ti3=(i); }                     \
      else { tv4=(v); ti4=(i); }                                                     \
    }                                                                                \
  }

// ---------------- A1: repack x -> Xk [b][c][j] (coalesced permutation copy) ------
__global__ void k_repack(const float* __restrict__ x){
  int idx = blockIdx.x*256 + threadIdx.x;          // float4 id; total 1,605,632
  int hw4 = idx % 196;
  int r   = idx / 196;
  int c   = r & 255;
  int bs  = r >> 8;
  int b = bs >> 3, t = bs & 7;
  float4 v = ((const float4*)x)[idx];
  ((float4*)g_Xk)[(b*CCH + c)*1568 + t*196 + hw4] = v;
}

// ---------------- A2: tiled transpose x -> Xt [b][j][c] ----------------
__global__ void k_xt(const float* __restrict__ x){
  __shared__ float tile[32][33];
  int bs = blockIdx.z, cb = blockIdx.y*32, hb = blockIdx.x*32;
  int tx = threadIdx.x, ty = threadIdx.y;
  #pragma unroll
  for (int q=0;q<4;q++){
    int c = cb + ty + q*8, hw = hb + tx;
    if (hw < HWP) tile[ty+q*8][tx] = x[((size_t)bs*CCH + c)*HWP + hw];
  }
  __syncthreads();
  int b = bs >> 3, t = bs & 7;
  #pragma unroll
  for (int q=0;q<4;q++){
    int hw = hb + ty + q*8, c = cb + tx;
    if (hw < HWP) g_Xt[((size_t)b*THWC + t*HWP + hw)*CCH + c] = tile[tx][ty+q*8];
  }
}

// ---------------- A3: per-column inverse norms ----------------
__global__ void k_norm(){
  int w = threadIdx.x >> 5, lane = threadIdx.x & 31;
  int row = blockIdx.x*8 + w;                      // 0..25087
  const float* rp = g_Xt + (size_t)row*CCH;
  float s = 0.f;
  #pragma unroll
  for (int q=0;q<8;q++){ float f = rp[lane + q*32]; s = fmaf(f, f, s); }
  #pragma unroll
  for (int o=16;o;o>>=1) s += __shfl_xor_sync(0xffffffffu, s, o);
  if (lane == 0) g_inv[row] = rsqrtf(s);
}

// ---------------- A4: transpose conv_w -> Wt [c][o] ----------------
__global__ void k_wt(const float* __restrict__ w){
  int c = blockIdx.x, o = threadIdx.x;
  g_Wt[c*CCH + o] = w[o*CCH + c];
}

// ---------------- B: Gram GEMM + fused streaming top-5 ----------------
// grid (49 j-tiles, 3 i-slices, 4 batches); 256 threads; 1 block/SM
__global__ void __launch_bounds__(256,1) k_corr(){
  extern __shared__ float sm[];
  float* Bs = sm;                    // [256][128] full-K j panel   (128 KB)
  float* As = sm + 32768;            // [2][16][128] A chunk ping-pong (16 KB)
  float* Sv = sm + 32768 + 4096;     // [128][129] scaled tile      (64.5 KB)
  __shared__ float s_invj[128];
  __shared__ float s_invi[128];

  const int tid = threadIdx.x;
  const int tx = tid & 15, ty = tid >> 4;
  const int jt = blockIdx.x, sl = blockIdx.y, b = blockIdx.z;
  const int jbase = jt*128;
  const int t0 = (sl==0) ? 0 : (17 + (sl-1)*16);
  const int nt = (sl==0) ? 17 : 16;
  const float* Xkb = g_Xk + (size_t)b*CCH*THWC;

  // load j panel: Bs[k][jj]
  #pragma unroll
  for (int q=0;q<32;q++){
    int id = tid + q*256;
    int k = id >> 5, jv = id & 31;
    ((float4*)Bs)[k*32 + jv] = *(const float4*)(Xkb + (size_t)k*THWC + jbase + jv*4);
  }
  if (tid < 128) s_invj[tid] = g_inv[b*THWC + jbase + tid];
  __syncthreads();

  const int col = tid & 127, half = tid >> 7;
  float tv0=-3e38f, tv1=-3e38f, tv2=-3e38f, tv3=-3e38f, tv4=-3e38f;
  int   ti0=0, ti1=0, ti2=0, ti3=0, ti4=0;

  for (int it = t0; it < t0 + nt; ++it){
    const int ibase = it*128;
    if (tid < 128) s_invi[tid] = g_inv[b*THWC + ibase + tid];

    // prologue: chunk 0 -> buffer 0
    {
      const float* src = Xkb + ibase;
      #pragma unroll
      for (int q=0;q<2;q++){
        int id = tid + q*256; int kk = id>>5, iv = id&31;
        cp16(As + kk*128 + iv*4, src + (size_t)kk*THWC + iv*4);
      }
      cp_commit();
    }

    float acc[8][8];
    #pragma unroll
    for (int r=0;r<8;r++)
      #pragma unroll
      for (int c=0;c<8;c++) acc[r][c] = 0.f;

    for (int kc=0; kc<16; ++kc){
      const int cur = kc & 1;
      if (kc < 15){
        const float* src = Xkb + (size_t)(kc+1)*16*THWC + ibase;
        float* dst = As + (cur^1)*2048;
        #pragma unroll
        for (int q=0;q<2;q++){
          int id = tid + q*256; int kk = id>>5, iv = id&31;
          cp16(dst + kk*128 + iv*4, src + (size_t)kk*THWC + iv*4);
        }
        cp_commit();
        cp_wait<1>();
      } else {
        cp_wait<0>();
      }
      __syncthreads();

      const float* Ab = As + cur*2048;
      #pragma unroll
      for (int kk=0;kk<16;kk++){
        float4 a0 = *(const float4*)(Ab + kk*128 + ty*8);
        float4 a1 = *(const float4*)(Ab + kk*128 + ty*8 + 4);
        const float* Bp = Bs + (kc*16+kk)*128 + tx*8;
        float4 b0 = *(const float4*)(Bp);
        float4 b1 = *(const float4*)(Bp + 4);
        float av[8] = {a0.x,a0.y,a0.z,a0.w,a1.x,a1.y,a1.z,a1.w};
        float bv[8] = {b0.x,b0.y,b0.z,b0.w,b1.x,b1.y,b1.z,b1.w};
        #pragma unroll
        for (int r=0;r<8;r++)
          #pragma unroll
          for (int c=0;c<8;c++)
            acc[r][c] = fmaf(av[r], bv[c], acc[r][c]);
      }
      __syncthreads();
    }

    // epilogue: scale by inverse norms, mask same-frame blocks, stage to Sv
    // (8-row / 8-col micro-tiles never cross a 784-frame boundary: 8 | 784)
    const bool masked = ((ibase + ty*8)/HWP) == ((jbase + tx*8)/HWP);
    #pragma unroll
    for (int r=0;r<8;r++){
      float ivn = s_invi[ty*8 + r];
      #pragma unroll
      for (int c=0;c<8;c++){
        float v = masked ? -1.0f : acc[r][c]*ivn*s_invj[tx*8+c];
        Sv[(ty*8+r)*129 + tx*8 + c] = v;
      }
    }
    __syncthreads();

    // streaming scan: 2 threads per column, 64 ascending rows each
    const int rbase = half*64;
    #pragma unroll 4
    for (int r=0;r<64;r++){
      float v = Sv[(rbase+r)*129 + col];
      int gi = ibase + rbase + r;
      INS5(v, gi);
    }
    __syncthreads();
  }

  // merge halves (reuse Sv as staging), write slice partials
  float* shv = Sv;
  int*   shi = (int*)(Sv + 128*TK);
  if (half == 1){
    shv[col*5+0]=tv0; shv[col*5+1]=tv1; shv[col*5+2]=tv2; shv[col*5+3]=tv3; shv[col*5+4]=tv4;
    shi[col*5+0]=ti0; shi[col*5+1]=ti1; shi[col*5+2]=ti2; shi[col*5+3]=ti3; shi[col*5+4]=ti4;
  }
  __syncthreads();
  if (half == 0){
    #pragma unroll
    for (int q=0;q<5;q++){ float v = shv[col*5+q]; int i = shi[col*5+q]; MINS5(v, i); }
    size_t base = ((size_t)(b*3 + sl)*THWC + jbase + col)*TK;
    g_pv[base+0]=tv0; g_pv[base+1]=tv1; g_pv[base+2]=tv2; g_pv[base+3]=tv3; g_pv[base+4]=tv4;
    g_pi[base+0]=ti0; g_pi[base+1]=ti1; g_pi[base+2]=ti2; g_pi[base+3]=ti3; g_pi[base+4]=ti4;
  }
}

// ---------------- C: merge 3 slice-partials -> final top-5 indices ----------------
__global__ void k_merge(){
  int gj = blockIdx.x*256 + threadIdx.x;   // 0..25087
  int b = gj / THWC, j = gj - b*THWC;
  float tv0=-3e38f, tv1=-3e38f, tv2=-3e38f, tv3=-3e38f, tv4=-3e38f;
  int   ti0=0, ti1=0, ti2=0, ti3=0, ti4=0;
  #pragma unroll
  for (int sl=0;sl<3;sl++){
    size_t base = ((size_t)(b*3 + sl)*THWC + j)*TK;
    #pragma unroll
    for (int q=0;q<5;q++){
      float v = g_pv[base+q]; int i = g_pi[base+q];
      MINS5(v, i);
    }
  }
  g_top[(size_t)gj*5+0]=ti0; g_top[(size_t)gj*5+1]=ti1; g_top[(size_t)gj*5+2]=ti2;
  g_top[(size_t)gj*5+3]=ti3; g_top[(size_t)gj*5+4]=ti4;
}

// ---------------- D: gather 5 columns, elementwise channel max ----------------
__global__ void k_gather(){
  int warp = threadIdx.x >> 5, lane = threadIdx.x & 31;
  int n = blockIdx.x*8 + warp;             // 0..25087
  int b = n / THWC;
  const int* tp = g_top + (size_t)n*5;
  int i0 = tp[0], i1 = tp[1], i2 = tp[2], i3 = tp[3], i4 = tp[4];
  const float4* X = (const float4*)(g_Xt + (size_t)b*THWC*CCH);
  float4* Yo = (float4*)(g_Y + (size_t)n*CCH);
  #pragma unroll
  for (int q=0;q<2;q++){
    int p = lane + q*32;                   // 0..63 float4 within a 256-float row
    float4 m  = X[(size_t)i0*64 + p];
    float4 v1 = X[(size_t)i1*64 + p];
    float4 v2 = X[(size_t)i2*64 + p];
    float4 v3 = X[(size_t)i3*64 + p];
    float4 v4 = X[(size_t)i4*64 + p];
    m.x = fmaxf(fmaxf(fmaxf(m.x,v1.x), fmaxf(v2.x,v3.x)), v4.x);
    m.y = fmaxf(fmaxf(fmaxf(m.y,v1.y), fmaxf(v2.y,v3.y)), v4.y);
    m.z = fmaxf(fmaxf(fmaxf(m.z,v1.z), fmaxf(v2.z,v3.z)), v4.z);
    m.w = fmaxf(fmaxf(fmaxf(m.w,v1.w), fmaxf(v2.w,v3.w)), v4.w);
    Yo[p] = m;
  }
}

// ---------------- E: BN statistics ----------------
__global__ void k_bnstat(){
  int t = threadIdx.x;
  const float* Yp = g_Y + (size_t)blockIdx.x*256*CCH;
  float s = 0.f, sq = 0.f;
  for (int r=0;r<256;r++){
    float v = Yp[(size_t)r*CCH + t];
    s += v; sq = fmaf(v, v, sq);
  }
  g_part[blockIdx.x*512 + t]       = s;
  g_part[blockIdx.x*512 + 256 + t] = sq;
}

__global__ void k_bnfin(const float* __restrict__ gamma, const float* __restrict__ beta){
  int t = threadIdx.x;
  float s = 0.f, sq = 0.f;
  for (int blk=0;blk<98;blk++){
    s  += g_part[blk*512 + t];
    sq += g_part[blk*512 + 256 + t];
  }
  const float invN = 1.0f/25088.0f;
  float mean = s*invN;
  float var  = sq*invN - mean*mean;
  float a = gamma[t]*rsqrtf(var + 1e-5f);
  g_ab[t]       = a;
  g_ab[256 + t] = beta[t] - mean*a;
}

// ---------------- F: fused BN+relu + 1x1 conv GEMM + bias + residual -------------
// grid (196 n-tiles, 2 o-tiles); 256 threads
__global__ void __launch_bounds__(256,1) k_conv(const float* __restrict__ cbv,
                                                const float* __restrict__ x,
                                                float* __restrict__ out){
  extern __shared__ float sm[];
  float* Ws = sm;            // [256][128] weight panel [k][o]  (128 KB)
  float* As = sm + 32768;    // [128][16]  z chunk (8 KB, single buffer)
  __shared__ float s_a[256], s_b[256], s_cb[128];

  const int tid = threadIdx.x;
  const int tx = tid & 15, ty = tid >> 4;
  const int nbase = blockIdx.x*128, obase = blockIdx.y*128;

  #pragma unroll
  for (int q=0;q<32;q++){
    int id = tid + q*256; int k = id>>5, ov = id&31;
    ((float4*)Ws)[k*32 + ov] = *(const float4*)(g_Wt + k*CCH + obase + ov*4);
  }
  s_a[tid] = g_ab[tid];
  s_b[tid] = g_ab[256 + tid];
  if (tid < 128) s_cb[tid] = cbv[obase + tid];

  float acc[8][8];
  #pragma unroll
  for (int r=0;r<8;r++)
    #pragma unroll
    for (int c=0;c<8;c++) acc[r][c] = 0.f;

  const int nn = tid >> 1, hf = tid & 1;
  const float* Yrow = g_Y + (size_t)(nbase + nn)*CCH + hf*8;

  for (int kc=0;kc<16;kc++){
    __syncthreads();           // protect As from previous iteration's readers
    float4 v0 = *(const float4*)(Yrow + kc*16);
    float4 v1 = *(const float4*)(Yrow + kc*16 + 4);
    int kg = kc*16 + hf*8;
    float vv[8] = {v0.x,v0.y,v0.z,v0.w,v1.x,v1.y,v1.z,v1.w};
    float z[8];
    #pragma unroll
    for (int q=0;q<8;q++) z[q] = fmaxf(fmaf(vv[q], s_a[kg+q], s_b[kg+q]), 0.f);
    *(float4*)(As + nn*16 + hf*8)     = make_float4(z[0],z[1],z[2],z[3]);
    *(float4*)(As + nn*16 + hf*8 + 4) = make_float4(z[4],z[5],z[6],z[7]);
    __syncthreads();

    #pragma unroll
    for (int kk=0;kk<16;kk++){
      float av[8];
      #pragma unroll
      for (int r=0;r<8;r++) av[r] = As[(ty*8+r)*16 + kk];
      const float* Bp = Ws + (kc*16+kk)*128 + tx*8;
      float4 b0 = *(const float4*)(Bp);
      float4 b1 = *(const float4*)(Bp + 4);
      float bv[8] = {b0.x,b0.y,b0.z,b0.w,b1.x,b1.y,b1.z,b1.w};
      #pragma unroll
      for (int r=0;r<8;r++)
        #pragma unroll
        for (int c=0;c<8;c++)
          acc[r][c] = fmaf(av[r], bv[c], acc[r][c]);
    }
  }

  // epilogue: bias + residual, write NCHW (thread's 8 n stay in one frame: 8|784)
  const int n0 = nbase + ty*8;
  const int bs = n0 / HWP;
  const int hw0 = n0 - bs*HWP;
  const float* xb = x   + (size_t)bs*CCH*HWP;
  float*       ob = out + (size_t)bs*CCH*HWP;
  #pragma unroll
  for (int c=0;c<8;c++){
    int o = obase + tx*8 + c;
    float bias = s_cb[tx*8 + c];
    size_t off = (size_t)o*HWP + hw0;
    float4 i0 = *(const float4*)(xb + off);
    float4 i1 = *(const float4*)(xb + off + 4);
    float4 r0 = make_float4(acc[0][c]+bias+i0.x, acc[1][c]+bias+i0.y,
                            acc[2][c]+bias+i0.z, acc[3][c]+bias+i0.w);
    float4 r1 = make_float4(acc[4][c]+bias+i1.x, acc[5][c]+bias+i1.y,
                            acc[6][c]+bias+i1.z, acc[7][c]+bias+i1.w);
    *(float4*)(ob + off)     = r0;
    *(float4*)(ob + off + 4) = r1;
  }
}

// ---------------- launch ----------------
extern "C" void kernel_launch(void* const* d_in, const int* in_sizes, int n_in,
                              void* d_out, int out_size){
  (void)in_sizes; (void)n_in; (void)out_size;
  const float* x      = (const float*)d_in[0];
  const float* gamma  = (const float*)d_in[1];
  const float* beta   = (const float*)d_in[2];
  const float* conv_w = (const float*)d_in[3];
  const float* conv_b = (const float*)d_in[4];
  float* out = (float*)d_out;

  cudaFuncSetAttribute(k_corr, cudaFuncAttributeMaxDynamicSharedMemorySize, 213504);
  cudaFuncSetAttribute(k_conv, cudaFuncAttributeMaxDynamicSharedMemorySize, 139264);

  k_repack<<<6272, 256>>>(x);
  k_xt<<<dim3(25, 8, 32), dim3(32, 8)>>>(x);
  k_norm<<<3136, 256>>>();
  k_wt<<<256, 256>>>(conv_w);
  k_corr<<<dim3(49, 3, 4), 256, 213504>>>();
  k_merge<<<98, 256>>>();
  k_gather<<<3136, 256>>>();
  k_bnstat<<<98, 256>>>();
  k_bnfin<<<1, 256>>>(gamma, beta);
  k_conv<<<dim3(196, 2), 256, 139264>>>(conv_b, x, out);
}